// round 16
// baseline (speedup 1.0000x reference)
#include <cuda_runtime.h>
#include <cuda_bf16.h>
#include <math.h>
#include <stdint.h>

// ============================================================================
// CTC decoder, round 16: scan split into a 5-kernel chain so the heavy phases
// run on 256 blocks (B x SEGS) instead of 32.
//   prep  : out=LOGZERO, g_sumexp=0, x/W fp32->bf16
//   gemm  : 128x128x64 bf16 m16n8k16, 3-stage ring, fused epilogue (best)
//   scanA : per-batch lastP1 prefix sum                       (grid B)
//   scanB : per-segment log-semiring map composition          (grid B x 8)
//   scanC : propagate state through segment maps              (grid B)
//   scanD : replay + online per-segment logsumexp             (grid B x 8)
//   scanE : combine partials, write beam/eos/blank            (grid B)
// ============================================================================

#define LOGZERO (-4290774016.0f)
#define SEGS 8

__device__ float g_sumexp[32768];
__device__ float g_blank[32768];
__device__ float g_beam[32768 * 32];
__device__ float g_cum[32768];
__device__ float g_map[32 * SEGS * 5 * 32];
__device__ float g_state[32 * SEGS * 2 * 32];
__device__ float g_pmax[32 * SEGS * 32];
__device__ float g_psum[32 * SEGS * 32];
__device__ __align__(16) __nv_bfloat16 g_xb[16384 * 512];
__device__ __align__(16) __nv_bfloat16 g_wb[4096 * 512];

// ---------------------------------------------------------------- helpers
__device__ __forceinline__ uint32_t smem_u32(const void* p) {
    uint32_t a;
    asm("{ .reg .u64 t; cvta.to.shared.u64 t, %1; cvt.u32.u64 %0, t; }"
        : "=r"(a) : "l"(p));
    return a;
}
#define CP_ASYNC16(dst, src) \
    asm volatile("cp.async.cg.shared.global [%0], [%1], 16;" :: "r"(dst), "l"(src))
#define CP_COMMIT() asm volatile("cp.async.commit_group;" ::: "memory")
#define CP_WAIT(n)  asm volatile("cp.async.wait_group %0;" :: "n"(n) : "memory")

__device__ __forceinline__ void ldmatrix_x4(uint32_t& r0, uint32_t& r1,
                                            uint32_t& r2, uint32_t& r3, uint32_t a) {
    asm volatile("ldmatrix.sync.aligned.m8n8.x4.shared.b16 {%0,%1,%2,%3}, [%4];"
                 : "=r"(r0), "=r"(r1), "=r"(r2), "=r"(r3) : "r"(a));
}
__device__ __forceinline__ void mma_bf16(float* c, const uint32_t* a, const uint32_t* b) {
    asm volatile(
        "mma.sync.aligned.m16n8k16.row.col.f32.bf16.bf16.f32 "
        "{%0,%1,%2,%3}, {%4,%5,%6,%7}, {%8,%9}, {%0,%1,%2,%3};"
        : "+f"(c[0]), "+f"(c[1]), "+f"(c[2]), "+f"(c[3])
        : "r"(a[0]), "r"(a[1]), "r"(a[2]), "r"(a[3]), "r"(b[0]), "r"(b[1]));
}

__device__ __forceinline__ float laexp(float a, float b) {
    float m = fmaxf(a, b);
    float d = fminf(a, b) - m;
    return m + __logf(1.0f + __expf(d));
}

// ---------------------------------------------------------------- prep
__global__ void prep_kernel(const float* __restrict__ x, const float* __restrict__ W,
                            float* __restrict__ out, int nx, int nw, int outN, int M) {
    int idx = blockIdx.x * blockDim.x + threadIdx.x;
    if (idx < outN) out[idx] = LOGZERO;
    if (idx < M)    g_sumexp[idx] = 0.0f;
    int i4 = idx << 2;
    if (i4 < nx) {
        float4 v = *reinterpret_cast<const float4*>(x + i4);
        *reinterpret_cast<__nv_bfloat162*>(g_xb + i4)     = __floats2bfloat162_rn(v.x, v.y);
        *reinterpret_cast<__nv_bfloat162*>(g_xb + i4 + 2) = __floats2bfloat162_rn(v.z, v.w);
    } else {
        int j4 = i4 - nx;
        if (j4 < nw) {
            float4 v = *reinterpret_cast<const float4*>(W + j4);
            *reinterpret_cast<__nv_bfloat162*>(g_wb + j4)     = __floats2bfloat162_rn(v.x, v.y);
            *reinterpret_cast<__nv_bfloat162*>(g_wb + j4 + 2) = __floats2bfloat162_rn(v.z, v.w);
        }
    }
}

// ---------------------------------------------------------------- GEMM (best)
#define BM 128
#define BN 128
#define BK 64
#define STRIDE 72
#define OPB    (BM * STRIDE * 2)
#define STAGE_B (2 * OPB)
#define NSTAGE 3
#define SM_BIAS (NSTAGE * STAGE_B)
#define SM_SLOT (SM_BIAS + 512)
#define SM_TOTAL (SM_SLOT + 512)

__global__ __launch_bounds__(256, 2)
void gemm_mma_kernel(const float* __restrict__ bias,
                     const int* __restrict__ beam, const int* __restrict__ blankp,
                     int M, int N, int K, int T, int CB) {
    extern __shared__ __align__(16) char smem[];
    float* sbias = reinterpret_cast<float*>(smem + SM_BIAS);
    int*   sslot = reinterpret_cast<int*>(smem + SM_SLOT);

    const int tid  = threadIdx.x;
    const int lane = tid & 31;
    const int wid  = tid >> 5;
    const int wm   = wid & 3;
    const int wn   = wid >> 2;
    const int bm   = blockIdx.y << 7;
    const int bn   = blockIdx.x << 7;
    const int bcta = bm / T;

    if (tid < BN) {
        sbias[tid] = bias[bn + tid];
        sslot[tid] = -1;
    }
    __syncthreads();
    if (tid <= CB) {
        int col = (tid < CB) ? beam[bcta * CB + tid] : (blankp ? blankp[0] : 0);
        if ((unsigned)(col - bn) < (unsigned)BN) sslot[col - bn] = tid;  // CB = blank
    }

    const int l_row = tid >> 3;
    const int l_c8  = (tid & 7) << 3;
    const __nv_bfloat16* gA = g_xb + (size_t)(bm + l_row) * K + l_c8;
    const __nv_bfloat16* gB = g_wb + (size_t)(bn + l_row) * K + l_c8;

    const uint32_t sm_u32 = smem_u32(smem);
    const uint32_t dA = sm_u32 + (uint32_t)(l_row * STRIDE + l_c8) * 2;
    const uint32_t dB = dA + OPB;
    const size_t gp = (size_t)32 * K;
    const uint32_t sp = 32 * STRIDE * 2;

    const int NC = K >> 6;

#pragma unroll
    for (int c = 0; c < 2; c++) {
        if (c < NC) {
            uint32_t sb = (uint32_t)c * STAGE_B;
            const __nv_bfloat16* a = gA + (size_t)c * BK;
            const __nv_bfloat16* b = gB + (size_t)c * BK;
#pragma unroll
            for (int p = 0; p < 4; p++) {
                CP_ASYNC16(dA + sb + p * sp, a + p * gp);
                CP_ASYNC16(dB + sb + p * sp, b + p * gp);
            }
        }
        CP_COMMIT();
    }

    float acc[2][8][4];
#pragma unroll
    for (int mt = 0; mt < 2; mt++)
#pragma unroll
        for (int nt = 0; nt < 8; nt++)
#pragma unroll
            for (int i = 0; i < 4; i++) acc[mt][nt][i] = 0.0f;

    const int a_row  = wm * 32 + (lane & 15);
    const int a_koff = (lane >> 4) << 3;
    const int b_row  = wn * 64 + ((lane >> 4) << 3) + (lane & 7);
    const int b_koff = ((lane >> 3) & 1) << 3;

    int s_cur = 0, s_nxt2 = 2;
    for (int c = 0; c < NC; c++) {
        CP_WAIT(1);
        __syncthreads();

        if (c + 2 < NC) {
            uint32_t sb = (uint32_t)s_nxt2 * STAGE_B;
            const __nv_bfloat16* a = gA + (size_t)(c + 2) * BK;
            const __nv_bfloat16* b = gB + (size_t)(c + 2) * BK;
#pragma unroll
            for (int p = 0; p < 4; p++) {
                CP_ASYNC16(dA + sb + p * sp, a + p * gp);
                CP_ASYNC16(dB + sb + p * sp, b + p * gp);
            }
        }
        CP_COMMIT();

        const uint32_t abase = sm_u32 + (uint32_t)s_cur * STAGE_B;
        const uint32_t bbase = abase + OPB;

#pragma unroll
        for (int kt = 0; kt < 4; kt++) {
            uint32_t af[2][4];
#pragma unroll
            for (int mt = 0; mt < 2; mt++) {
                uint32_t addr = abase +
                    (uint32_t)((a_row + mt * 16) * STRIDE + kt * 16 + a_koff) * 2;
                ldmatrix_x4(af[mt][0], af[mt][1], af[mt][2], af[mt][3], addr);
            }
            uint32_t bf[8][2];
#pragma unroll
            for (int nt2 = 0; nt2 < 4; nt2++) {
                uint32_t addr = bbase +
                    (uint32_t)((b_row + nt2 * 16) * STRIDE + kt * 16 + b_koff) * 2;
                uint32_t r0, r1, r2, r3;
                ldmatrix_x4(r0, r1, r2, r3, addr);
                bf[nt2 * 2][0] = r0;      bf[nt2 * 2][1] = r1;
                bf[nt2 * 2 + 1][0] = r2;  bf[nt2 * 2 + 1][1] = r3;
            }
#pragma unroll
            for (int mt = 0; mt < 2; mt++)
#pragma unroll
                for (int nt = 0; nt < 8; nt++)
                    mma_bf16(acc[mt][nt], af[mt], bf[nt]);
        }

        if (++s_cur == NSTAGE) s_cur = 0;
        if (++s_nxt2 == NSTAGE) s_nxt2 = 0;
    }

    const int gq = lane >> 2;
    const int qc = (lane & 3) << 1;
#pragma unroll
    for (int mt = 0; mt < 2; mt++) {
        const int r0 = bm + wm * 32 + mt * 16 + gq;
        float s0 = 0.0f, s1 = 0.0f;
#pragma unroll
        for (int nt = 0; nt < 8; nt++) {
            const int c0 = wn * 64 + nt * 8 + qc;
            float b0 = sbias[c0];
            float b1 = sbias[c0 + 1];
            float v00 = acc[mt][nt][0] + b0;
            float v01 = acc[mt][nt][1] + b1;
            float v10 = acc[mt][nt][2] + b0;
            float v11 = acc[mt][nt][3] + b1;
            s0 += __expf(v00) + __expf(v01);
            s1 += __expf(v10) + __expf(v11);
            int sl0 = sslot[c0], sl1 = sslot[c0 + 1];
            if (sl0 >= 0) {
                if (sl0 == CB) { g_blank[r0] = v00; g_blank[r0 + 8] = v10; }
                else { g_beam[(size_t)r0 * CB + sl0] = v00;
                       g_beam[(size_t)(r0 + 8) * CB + sl0] = v10; }
            }
            if (sl1 >= 0) {
                if (sl1 == CB) { g_blank[r0] = v01; g_blank[r0 + 8] = v11; }
                else { g_beam[(size_t)r0 * CB + sl1] = v01;
                       g_beam[(size_t)(r0 + 8) * CB + sl1] = v11; }
            }
        }
        s0 += __shfl_xor_sync(0xffffffffu, s0, 1);
        s0 += __shfl_xor_sync(0xffffffffu, s0, 2);
        s1 += __shfl_xor_sync(0xffffffffu, s1, 1);
        s1 += __shfl_xor_sync(0xffffffffu, s1, 2);
        if ((lane & 3) == 0) {
            atomicAdd(&g_sumexp[r0], s0);
            atomicAdd(&g_sumexp[r0 + 8], s1);
        }
    }
}

// ---------------------------------------------------------------- scanA
// per-batch inclusive prefix sum of blank log-probs (lastP1) -> g_cum
__global__ void scanA_kernel(int T) {
    __shared__ float s_lpb[512];
    __shared__ float s_red[2 * SEGS];
    const int b = blockIdx.x;
    const int tid = threadIdx.x;
    const int LEN = T / SEGS;

    for (int t = tid; t < T; t += blockDim.x)
        s_lpb[t] = g_blank[b * T + t] - __logf(g_sumexp[b * T + t]);
    __syncthreads();
    if (tid < SEGS) {
        float p = 0.0f;
        for (int t = tid * LEN; t < (tid + 1) * LEN; t++) p += s_lpb[t];
        s_red[tid] = p;
    }
    __syncthreads();
    if (tid == 0) {
        float run = 0.0f;
        for (int k = 0; k < SEGS; k++) { s_red[SEGS + k] = run; run += s_red[k]; }
    }
    __syncthreads();
    if (tid < SEGS) {
        float c = s_red[SEGS + tid];
        for (int t = tid * LEN; t < (tid + 1) * LEN; t++) {
            c += s_lpb[t];
            g_cum[b * T + t] = c;
        }
    }
}

// ---------------------------------------------------------------- scanB
// Map rep (a,c,d,e,f): Pn' = laexp(a+Pn, e); Pb' = laexp(laexp(c+Pn, d+Pb), f).
__global__ void scanB_kernel(int T, int CB, int Ly) {
    const int b = blockIdx.x;
    const int s = blockIdx.y;
    const int j = threadIdx.x;              // 32
    const int LEN = T / SEGS;
    const int t0 = s * LEN, t1 = t0 + LEN;
    const int start = Ly < (T - 1) ? Ly : (T - 1);
    const int loop_start = start > 1 ? start : 1;

    float a = 0.0f, c = LOGZERO, d = 0.0f, e = LOGZERO, f = LOGZERO;
#pragma unroll 4
    for (int t = t0; t < t1; t++) {
        if (t < loop_start) {
            if (start == 0 && t == 0) {
                float lse0 = __logf(g_sumexp[b * T]);
                float xn0 = (j < CB) ? g_beam[(size_t)(b * T) * CB + j] - lse0 : LOGZERO;
                a = LOGZERO; c = LOGZERO; d = LOGZERO; e = xn0; f = LOGZERO;
            }
            continue;
        }
        float lse = __logf(g_sumexp[b * T + t]);
        float bl = g_blank[b * T + t] - lse;
        float xn = (j < CB) ? g_beam[(size_t)(b * T + t) * CB + j] - lse : LOGZERO;
        float pref = g_cum[b * T + t - 1];
        float ac = laexp(a, c);
        float ep = laexp(e, pref);
        float ef = laexp(e, f);
        a = xn + a;
        c = bl + ac;
        d = bl + d;
        e = xn + ep;
        f = bl + ef;
    }
    int base = ((b * SEGS + s) * 5) * 32 + j;
    g_map[base]       = a;
    g_map[base + 32]  = c;
    g_map[base + 64]  = d;
    g_map[base + 96]  = e;
    g_map[base + 128] = f;
}

// ---------------------------------------------------------------- scanC
__global__ void scanC_kernel(int T) {
    const int b = blockIdx.x;
    const int j = threadIdx.x;               // 32
    float Pn = LOGZERO, Pb = LOGZERO;
    for (int k = 0; k < SEGS; k++) {
        int sb = ((b * SEGS + k) * 2) * 32 + j;
        g_state[sb]      = Pn;
        g_state[sb + 32] = Pb;
        int mb = ((b * SEGS + k) * 5) * 32 + j;
        float a = g_map[mb], c = g_map[mb + 32], d = g_map[mb + 64];
        float e = g_map[mb + 96], f = g_map[mb + 128];
        float Pn2 = laexp(a + Pn, e);
        float Pb2 = laexp(laexp(c + Pn, d + Pb), f);
        Pn = Pn2; Pb = Pb2;
    }
}

// ---------------------------------------------------------------- scanD
// replay segment from incoming state with online masked logsumexp
__global__ void scanD_kernel(const int* __restrict__ xl, int T, int CB, int Ly) {
    const int b = blockIdx.x;
    const int s = blockIdx.y;
    const int j = threadIdx.x;               // 32
    const int LEN = T / SEGS;
    const int t0 = s * LEN, t1 = t0 + LEN;
    const int start = Ly < (T - 1) ? Ly : (T - 1);
    const int loop_start = start > 1 ? start : 1;
    const int xlb = xl[b];

    int sb = ((b * SEGS + s) * 2) * 32 + j;
    float Pn = g_state[sb], Pb = g_state[sb + 32];
    float mx = LOGZERO, sm = 0.0f;

#pragma unroll 4
    for (int t = t0; t < t1; t++) {
        float na;
        if (t < loop_start) {
            if (start == 0 && t == 0) {
                float lse0 = __logf(g_sumexp[b * T]);
                Pn = (j < CB) ? g_beam[(size_t)(b * T) * CB + j] - lse0 : LOGZERO;
                Pb = LOGZERO;
                na = laexp(Pn, Pb);
            } else {
                na = LOGZERO;
            }
        } else {
            float lse = __logf(g_sumexp[b * T + t]);
            float bl = g_blank[b * T + t] - lse;
            float xn = (j < CB) ? g_beam[(size_t)(b * T + t) * CB + j] - lse : LOGZERO;
            float pref = g_cum[b * T + t - 1];
            float pn = xn + laexp(Pn, pref);
            float pb = bl + laexp(Pn, Pb);
            Pn = pn; Pb = pb;
            na = laexp(pn, pb);
        }
        if (t >= start && t < xlb) {          // uniform across warp
            float m2 = fmaxf(mx, na);
            sm = sm * __expf(mx - m2) + __expf(na - m2);
            mx = m2;
        }
    }
    g_pmax[(b * SEGS + s) * 32 + j] = mx;
    g_psum[(b * SEGS + s) * 32 + j] = sm;
}

// ---------------------------------------------------------------- scanE
__global__ void scanE_kernel(const int* __restrict__ xl, const int* __restrict__ beam,
                             const int* __restrict__ blankp, const int* __restrict__ eosp,
                             float* __restrict__ out, int T, int V, int CB) {
    const int b = blockIdx.x;
    const int j = threadIdx.x;               // 32
    const int blankv = blankp ? blankp[0] : 0;
    const int eosv   = eosp ? eosp[0] : (V - 1);
    const int xlb = xl[b];

    float Mall = LOGZERO;
#pragma unroll
    for (int k = 0; k < SEGS; k++)
        Mall = fmaxf(Mall, g_pmax[(b * SEGS + k) * 32 + j]);
    float tot = 0.0f;
#pragma unroll
    for (int k = 0; k < SEGS; k++) {
        float mk = g_pmax[(b * SEGS + k) * 32 + j];
        float sk = g_psum[(b * SEGS + k) * 32 + j];
        tot += sk * __expf(mk - Mall);
    }
    float accv = (tot > 0.0f) ? (Mall + __logf(tot)) : LOGZERO;
    if (j < CB) out[(size_t)b * V + beam[b * CB + j]] = accv;
    __syncthreads();                          // order beam writes before eos/blank
    if (j == 0) {
        float eosval = (xlb >= 1 && xlb <= T) ? g_cum[b * T + xlb - 1] : 0.0f;
        out[(size_t)b * V + eosv]   = eosval;
        out[(size_t)b * V + blankv] = LOGZERO;
    }
}

// ---------------------------------------------------------------------------
extern "C" void kernel_launch(void* const* d_in, const int* in_sizes, int n_in,
                              void* d_out, int out_size) {
    const float* x    = (const float*)d_in[0];   // (B,T,D)
    const float* W    = (const float*)d_in[1];   // (V,D)
    const float* bias = (const float*)d_in[2];   // (V,)
    const int*   xl   = (const int*)d_in[3];     // (B,)
    // d_in[4] = y : unused (lastPsum == lastP1 in f32, branch collapses)
    const int*   beam = (const int*)d_in[5];     // (B,CB)
    const int*   blankp = (n_in > 6) ? (const int*)d_in[6] : nullptr;
    const int*   eosp   = (n_in > 7) ? (const int*)d_in[7] : nullptr;

    const int B  = in_sizes[3];
    const int V  = in_sizes[2];
    const int D  = in_sizes[1] / V;
    const int T  = in_sizes[0] / (B * D);
    const int CB = in_sizes[5] / B;
    const int Ly = in_sizes[4] / B;
    const int M  = B * T;

    float* out = (float*)d_out;

    const int nx = M * D, nw = V * D;
    int nthr = (nx + nw) >> 2;
    if (nthr < out_size) nthr = out_size;
    prep_kernel<<<(nthr + 255) / 256, 256>>>(x, W, out, nx, nw, out_size, M);

    cudaFuncSetAttribute(gemm_mma_kernel,
                         cudaFuncAttributeMaxDynamicSharedMemorySize, SM_TOTAL);
    dim3 gg(V >> 7, M >> 7);
    gemm_mma_kernel<<<gg, 256, SM_TOTAL>>>(bias, beam, blankp, M, V, D, T, CB);

    scanA_kernel<<<B, 256>>>(T);
    dim3 gseg(B, SEGS);
    scanB_kernel<<<gseg, 32>>>(T, CB, Ly);
    scanC_kernel<<<B, 32>>>(T);
    scanD_kernel<<<gseg, 32>>>(xl, T, CB, Ly);
    scanE_kernel<<<B, 32>>>(xl, beam, blankp, eosp, out, T, V, CB);
}